// round 8
// baseline (speedup 1.0000x reference)
#include <cuda_runtime.h>
#include <math.h>

#define BATCH 16
#define CCH   256
#define HWSZ  16384
#define RED   64
#define MID   32
#define NWIN  4096
#define ATT_SCALE 0.35355339059327373f   // 8^-0.5

typedef unsigned long long u64t;

// Folded weights (prepared by k_prep) — plain float, transposed
__device__ float g_W1t[CCH * RED];   // [c][o]
__device__ float g_b1[RED];
__device__ float g_W2t[RED * CCH];   // [r][o]
__device__ float g_b2[CCH];
__device__ float g_Wqkt[MID * 64];   // [k][o]  o<32: q_head, o>=32: k_head
__device__ float g_bqk[64];

__device__ __forceinline__ u64t pk(float a) {
    u64t r; asm("mov.b64 %0, {%1,%1};" : "=l"(r) : "f"(a)); return r;
}
__device__ __forceinline__ void f2fma(u64t& d, u64t a, u64t b) {
    asm("fma.rn.f32x2 %0, %1, %2, %0;" : "+l"(d) : "l"(a), "l"(b));
}
__device__ __forceinline__ void f2add(u64t& d, u64t a) {
    asm("add.rn.f32x2 %0, %0, %1;" : "+l"(d) : "l"(a));
}
__device__ __forceinline__ float2 up(u64t a) {
    float2 f; asm("mov.b64 {%0, %1}, %2;" : "=f"(f.x), "=f"(f.y) : "l"(a)); return f;
}

// ---------------------------------------------------------------------------
__global__ void k_prep(const float* __restrict__ gin,  const float* __restrict__ bin,
                       const float* __restrict__ min_, const float* __restrict__ vin,
                       const float* __restrict__ w_in, const float* __restrict__ w_out,
                       const float* __restrict__ gout, const float* __restrict__ bout,
                       const float* __restrict__ mout, const float* __restrict__ vout,
                       const float* __restrict__ alpha,
                       const float* __restrict__ qh,   const float* __restrict__ qb,
                       const float* __restrict__ kh,   const float* __restrict__ kb)
{
    int tid = threadIdx.x;
    float s = 1.f / (1.f + expf(-alpha[0]));

    for (int idx = tid; idx < CCH * RED; idx += 256) {
        int c = idx >> 6, o = idx & 63;
        float inv = gin[c] * rsqrtf(vin[c] + 1e-5f);
        g_W1t[idx] = w_in[o * CCH + c] * inv;
    }
    if (tid < RED) {
        float a = 0.f;
        for (int c = 0; c < CCH; c++) {
            float inv = gin[c] * rsqrtf(vin[c] + 1e-5f);
            a += w_in[tid * CCH + c] * (bin[c] - min_[c] * inv);
        }
        g_b1[tid] = a;
    }
    for (int idx = tid; idx < RED * CCH; idx += 256) {
        int r = idx >> 8, o = idx & 255;
        float inv = gout[o] * rsqrtf(vout[o] + 1e-5f);
        g_W2t[idx] = s * inv * w_out[o * RED + r];
    }
    if (tid < 256) {
        float inv = gout[tid] * rsqrtf(vout[tid] + 1e-5f);
        g_b2[tid] = s * (bout[tid] - mout[tid] * inv);
    }
    for (int idx = tid; idx < MID * 64; idx += 256) {
        int k = idx >> 6, o = idx & 63;
        g_Wqkt[idx] = (o < 32) ? qh[o * 32 + k] : kh[(o - 32) * 32 + k];
    }
    if (tid < 64) g_bqk[tid] = (tid < 32) ? qb[tid] : kb[tid - 32];
}

// ---------------------------------------------------------------------------
// SMEM layout (floats), phase-overlaid:
//   A: xchunk(4096) -> partials(4352) -> Wqk(2048) -> S(64x68) -> partials
//   B: W stage(4096) -> [qs|ks](4096) -> W2 stage(4096)
//   C: xr(4096) -> attout(4096)
//   D: base(2048) -> outs(2048)
//   U: vs(2048)
// ---------------------------------------------------------------------------
#define SM_A    0
#define SM_B    4352
#define SM_C    8448
#define SM_D    12544
#define SM_U    14592
#define SM_WQK  16640
#define SM_WV   17152
#define SM_WO   17664
#define SM_BQK  18176
#define SM_BV   18240
#define SM_BO   18272
#define SM_B1   18336
#define SM_B2   18400
#define SM_TOTAL 18656   // 74624 bytes -> 3 CTAs/SM

__global__ __launch_bounds__(256, 3) void k_fused(
    const float* __restrict__ x, float* __restrict__ out,
    const float* __restrict__ wqk_g, const float* __restrict__ wv_g,
    const float* __restrict__ vb_g,  const float* __restrict__ wo_g,
    const float* __restrict__ ob_g)
{
    extern __shared__ float sm[];
    const int tid = threadIdx.x;
    const int bw = blockIdx.x;
    const int b  = bw >> 8;
    const int hb = (bw >> 4) & 15;
    const int wb = bw & 15;
    const long winbase = (long)(hb * 8) * 128 + wb * 8;
    const long xwin = (long)b * CCH * HWSZ + winbase;

    // ---- weights to smem ----
    for (int i = tid; i < 512; i += 256) {
        sm[SM_WQK + i] = wqk_g[i];
        sm[SM_WV + i]  = wv_g[i];
        sm[SM_WO + i]  = wo_g[i];
    }
    if (tid < 64)       sm[SM_BQK + tid] = g_bqk[tid];
    else if (tid < 96)  sm[SM_BV + tid - 64] = vb_g[tid - 64];
    else if (tid < 160) sm[SM_BO + tid - 96] = ob_g[tid - 96];
    else if (tid < 224) sm[SM_B1 + tid - 160] = g_b1[tid - 160];
    sm[SM_B2 + tid] = g_b2[tid];

    // GEMM mapping (k-split): gid = K half, tile 4o x 8n per thread
    const int gid = tid >> 7;
    const int t   = tid & 127;
    const int o0  = (t >> 3) * 4;     // 0..60
    const int n0  = (t & 7) * 8;      // 0..56
    u64t* pb = (u64t*)(sm + SM_A);    // partial buffer, stride-17 u64

    // Attention mapping (R4): thread 4o x 4n
    const int oa = (tid >> 4) * 4;
    const int na = (tid & 15) * 4;

    // ================= in_proj: xr = W1t^T @ x_window (K=256) =================
    {
        u64t acc[2][8];
#pragma unroll
        for (int i = 0; i < 16; i++) acc[i >> 3][i & 7] = 0ull;

        for (int kc = 0; kc < 4; kc++) {
            for (int idx = tid; idx < 1024; idx += 256)
                ((float4*)(sm + SM_B))[idx] = ((const float4*)(g_W1t + kc * 4096))[idx];
            for (int idx = tid; idx < 1024; idx += 256) {
                int c = idx >> 4, q = idx & 15;
                ((float4*)(sm + SM_A))[idx] =
                    *(const float4*)&x[xwin + (long)(kc * 64 + c) * HWSZ + ((q >> 1) << 7) + ((q & 1) << 2)];
            }
            __syncthreads();
#pragma unroll 8
            for (int kk = 0; kk < 32; kk++) {
                int k = gid * 32 + kk;
                const u64t* wp = (const u64t*)(sm + SM_B + k * 64 + o0);
                u64t w0 = wp[0], w1 = wp[1];
                const float* xr_ = sm + SM_A + k * 64 + n0;
                float4 xa = *(const float4*)xr_;
                float4 xb = *(const float4*)(xr_ + 4);
                u64t x0 = pk(xa.x), x1 = pk(xa.y), x2 = pk(xa.z), x3 = pk(xa.w);
                u64t x4 = pk(xb.x), x5 = pk(xb.y), x6 = pk(xb.z), x7 = pk(xb.w);
                f2fma(acc[0][0], w0, x0); f2fma(acc[0][1], w0, x1);
                f2fma(acc[0][2], w0, x2); f2fma(acc[0][3], w0, x3);
                f2fma(acc[0][4], w0, x4); f2fma(acc[0][5], w0, x5);
                f2fma(acc[0][6], w0, x6); f2fma(acc[0][7], w0, x7);
                f2fma(acc[1][0], w1, x0); f2fma(acc[1][1], w1, x1);
                f2fma(acc[1][2], w1, x2); f2fma(acc[1][3], w1, x3);
                f2fma(acc[1][4], w1, x4); f2fma(acc[1][5], w1, x5);
                f2fma(acc[1][6], w1, x6); f2fma(acc[1][7], w1, x7);
            }
            __syncthreads();
        }
        // reduce the two K-halves
        if (gid) {
#pragma unroll
            for (int i = 0; i < 16; i++) pb[t * 17 + i] = acc[i >> 3][i & 7];
        }
        __syncthreads();
        if (!gid) {
#pragma unroll
            for (int op = 0; op < 2; op++) {
                u64t bd = *(const u64t*)(sm + SM_B1 + o0 + 2 * op);
#pragma unroll
                for (int j = 0; j < 8; j++) {
                    f2add(acc[op][j], pb[t * 17 + op * 8 + j]);
                    f2add(acc[op][j], bd);
                }
                float lo[8], hi[8];
#pragma unroll
                for (int j = 0; j < 8; j++) {
                    float2 v = up(acc[op][j]); lo[j] = v.x; hi[j] = v.y;
                }
                int ro = o0 + 2 * op;
                *(float4*)(sm + SM_C + ro * 64 + n0)       = make_float4(lo[0], lo[1], lo[2], lo[3]);
                *(float4*)(sm + SM_C + ro * 64 + n0 + 4)   = make_float4(lo[4], lo[5], lo[6], lo[7]);
                *(float4*)(sm + SM_C + (ro + 1) * 64 + n0)     = make_float4(hi[0], hi[1], hi[2], hi[3]);
                *(float4*)(sm + SM_C + (ro + 1) * 64 + n0 + 4) = make_float4(hi[4], hi[5], hi[6], hi[7]);
            }
        }
    }
    __syncthreads();

    // ====== base (wqk) + v (wv) grouped convs on xr; stage Wqkt -> A ======
    {
#pragma unroll
        for (int t2 = 0; t2 < 2; t2++) {
            int et = tid + 256 * t2;
            int m = et >> 4, nb = (et & 15) * 4, g = m >> 3;
            const float* wr1 = sm + SM_WQK + g * 128 + (m & 7) * 16;
            const float* wr2 = sm + SM_WV  + g * 128 + (m & 7) * 16;
            float bv = sm[SM_BV + m];
            float4 ab = make_float4(0.f, 0.f, 0.f, 0.f);
            float4 av = make_float4(bv, bv, bv, bv);
#pragma unroll
            for (int i = 0; i < 16; i++) {
                float w1 = wr1[i], w2 = wr2[i];
                float4 xv = *(const float4*)(sm + SM_C + (g * 16 + i) * 64 + nb);
                ab.x += w1 * xv.x; ab.y += w1 * xv.y; ab.z += w1 * xv.z; ab.w += w1 * xv.w;
                av.x += w2 * xv.x; av.y += w2 * xv.y; av.z += w2 * xv.z; av.w += w2 * xv.w;
            }
            *(float4*)(sm + SM_D + m * 64 + nb) = ab;
            *(float4*)(sm + SM_U + m * 64 + nb) = av;
        }
        const float4* src = (const float4*)g_Wqkt;
        for (int idx = tid; idx < 512; idx += 256)
            ((float4*)(sm + SM_A))[idx] = src[idx];
    }
    __syncthreads();

    // ========== q|k : dense 64x64, K=32 GEMM on base (R4 mapping) ==========
    {
        u64t acc[2][4] = {{0,0,0,0},{0,0,0,0}};
#pragma unroll 8
        for (int k = 0; k < 32; k++) {
            const u64t* wp = (const u64t*)(sm + SM_A + k * 64 + oa);
            u64t w0 = wp[0], w1 = wp[1];
            float4 xv = *(const float4*)(sm + SM_D + k * 64 + na);
            u64t x0 = pk(xv.x), x1 = pk(xv.y), x2 = pk(xv.z), x3 = pk(xv.w);
            f2fma(acc[0][0], w0, x0); f2fma(acc[0][1], w0, x1);
            f2fma(acc[0][2], w0, x2); f2fma(acc[0][3], w0, x3);
            f2fma(acc[1][0], w1, x0); f2fma(acc[1][1], w1, x1);
            f2fma(acc[1][2], w1, x2); f2fma(acc[1][3], w1, x3);
        }
        __syncthreads();   // done reading A (reused as S next)
#pragma unroll
        for (int op = 0; op < 2; op++) {
            float ba = sm[SM_BQK + oa + op * 2], bb = sm[SM_BQK + oa + op * 2 + 1];
#pragma unroll
            for (int j = 0; j < 4; j++) {
                float2 v = up(acc[op][j]);
                sm[SM_B + (oa + op * 2)     * 64 + na + j] = v.x + ba;
                sm[SM_B + (oa + op * 2 + 1) * 64 + na + j] = v.y + bb;
            }
        }
    }
    __syncthreads();

    // ================= attention, per head =================
    for (int h = 0; h < 4; h++) {
        // scores 4x4 register tile -> S (stride 68)
        {
            float sc[4][4];
#pragma unroll
            for (int a = 0; a < 4; a++)
#pragma unroll
                for (int c = 0; c < 4; c++) sc[a][c] = 0.f;
#pragma unroll
            for (int d = 0; d < 8; d++) {
                float4 q4 = *(const float4*)(sm + SM_B + (h * 8 + d) * 64 + oa);
                float4 k4 = *(const float4*)(sm + SM_B + 2048 + (h * 8 + d) * 64 + na);
                sc[0][0] += q4.x * k4.x; sc[0][1] += q4.x * k4.y; sc[0][2] += q4.x * k4.z; sc[0][3] += q4.x * k4.w;
                sc[1][0] += q4.y * k4.x; sc[1][1] += q4.y * k4.y; sc[1][2] += q4.y * k4.z; sc[1][3] += q4.y * k4.w;
                sc[2][0] += q4.z * k4.x; sc[2][1] += q4.z * k4.y; sc[2][2] += q4.z * k4.z; sc[2][3] += q4.z * k4.w;
                sc[3][0] += q4.w * k4.x; sc[3][1] += q4.w * k4.y; sc[3][2] += q4.w * k4.z; sc[3][3] += q4.w * k4.w;
            }
#pragma unroll
            for (int a = 0; a < 4; a++) {
                float4 ov = make_float4(sc[a][0] * ATT_SCALE, sc[a][1] * ATT_SCALE,
                                        sc[a][2] * ATT_SCALE, sc[a][3] * ATT_SCALE);
                *(float4*)(sm + SM_A + (oa + a) * 68 + na) = ov;
            }
        }
        __syncthreads();
        // softmax: 4 threads per row, shfl reduce
        {
            int row = tid >> 2, qd = tid & 3;
            float* Sr = sm + SM_A + row * 68 + qd * 16;
            float4 v0 = *(float4*)(Sr + 0), v1 = *(float4*)(Sr + 4);
            float4 v2 = *(float4*)(Sr + 8), v3 = *(float4*)(Sr + 12);
            float mx = fmaxf(fmaxf(fmaxf(v0.x, v0.y), fmaxf(v0.z, v0.w)),
                             fmaxf(fmaxf(v1.x, v1.y), fmaxf(v1.z, v1.w)));
            mx = fmaxf(mx, fmaxf(fmaxf(fmaxf(v2.x, v2.y), fmaxf(v2.z, v2.w)),
                                 fmaxf(fmaxf(v3.x, v3.y), fmaxf(v3.z, v3.w))));
            mx = fmaxf(mx, __shfl_xor_sync(0xffffffffu, mx, 1));
            mx = fmaxf(mx, __shfl_xor_sync(0xffffffffu, mx, 2));
            v0.x = __expf(v0.x - mx); v0.y = __expf(v0.y - mx); v0.z = __expf(v0.z - mx); v0.w = __expf(v0.w - mx);
            v1.x = __expf(v1.x - mx); v1.y = __expf(v1.y - mx); v1.z = __expf(v1.z - mx); v1.w = __expf(v1.w - mx);
            v2.x = __expf(v2.x - mx); v2.y = __expf(v2.y - mx); v2.z = __expf(v2.z - mx); v2.w = __expf(v2.w - mx);
            v3.x = __expf(v3.x - mx); v3.y = __expf(v3.y - mx); v3.z = __expf(v3.z - mx); v3.w = __expf(v3.w - mx);
            float s = (v0.x + v0.y + v0.z + v0.w) + (v1.x + v1.y + v1.z + v1.w)
                    + (v2.x + v2.y + v2.z + v2.w) + (v3.x + v3.y + v3.z + v3.w);
            s += __shfl_xor_sync(0xffffffffu, s, 1);
            s += __shfl_xor_sync(0xffffffffu, s, 2);
            float r = 1.f / s;
            v0.x *= r; v0.y *= r; v0.z *= r; v0.w *= r;
            v1.x *= r; v1.y *= r; v1.z *= r; v1.w *= r;
            v2.x *= r; v2.y *= r; v2.z *= r; v2.w *= r;
            v3.x *= r; v3.y *= r; v3.z *= r; v3.w *= r;
            *(float4*)(Sr + 0) = v0;  *(float4*)(Sr + 4) = v1;
            *(float4*)(Sr + 8) = v2;  *(float4*)(Sr + 12) = v3;
        }
        __syncthreads();
        // out = attn @ v : thread -> token i, rows r0, r0+1
        {
            int i = tid & 63, dq = tid >> 6;
            int r0 = h * 8 + dq * 2;
            const float* Sr = sm + SM_A + i * 68;
            float a0 = 0.f, a1 = 0.f;
#pragma unroll
            for (int j = 0; j < 64; j += 4) {
                float4 s4 = *(const float4*)(Sr + j);
                float4 w0 = *(const float4*)(sm + SM_U + r0 * 64 + j);
                float4 w1 = *(const float4*)(sm + SM_U + (r0 + 1) * 64 + j);
                a0 += s4.x * w0.x + s4.y * w0.y + s4.z * w0.z + s4.w * w0.w;
                a1 += s4.x * w1.x + s4.y * w1.y + s4.z * w1.z + s4.w * w1.w;
            }
            sm[SM_D + r0 * 64 + i]       = a0;
            sm[SM_D + (r0 + 1) * 64 + i] = a1;
        }
        __syncthreads();
    }

    // ========== o grouped conv (32 -> 64) -> attout in C ==========
#pragma unroll
    for (int t4 = 0; t4 < 4; t4++) {
        int et = tid + 256 * t4;
        int r = et >> 4, nb = (et & 15) * 4, g = r >> 4;
        const float* wr = sm + SM_WO + g * 128 + (r & 15) * 8;
        float bo = sm[SM_BO + r];
        float4 a = make_float4(bo, bo, bo, bo);
#pragma unroll
        for (int m = 0; m < 8; m++) {
            float w = wr[m];
            float4 xv = *(const float4*)(sm + SM_D + (g * 8 + m) * 64 + nb);
            a.x += w * xv.x; a.y += w * xv.y; a.z += w * xv.z; a.w += w * xv.w;
        }
        *(float4*)(sm + SM_C + r * 64 + nb) = a;
    }
    __syncthreads();

    // ========== out_proj (4 o-tiles of 64, K=64, k-split 32/32) ==========
    for (int ot = 0; ot < 4; ot++) {
        for (int idx = tid; idx < 1024; idx += 256) {
            int r = idx >> 4, oq = idx & 15;
            ((float4*)(sm + SM_B))[idx] =
                *(const float4*)&g_W2t[r * 256 + ot * 64 + oq * 4];
        }
        __syncthreads();
        u64t acc[2][8];
#pragma unroll
        for (int i = 0; i < 16; i++) acc[i >> 3][i & 7] = 0ull;
#pragma unroll 8
        for (int kk = 0; kk < 32; kk++) {
            int k = gid * 32 + kk;
            const u64t* wp = (const u64t*)(sm + SM_B + k * 64 + o0);
            u64t w0 = wp[0], w1 = wp[1];
            const float* xr_ = sm + SM_C + k * 64 + n0;
            float4 xa = *(const float4*)xr_;
            float4 xb = *(const float4*)(xr_ + 4);
            u64t x0 = pk(xa.x), x1 = pk(xa.y), x2 = pk(xa.z), x3 = pk(xa.w);
            u64t x4 = pk(xb.x), x5 = pk(xb.y), x6 = pk(xb.z), x7 = pk(xb.w);
            f2fma(acc[0][0], w0, x0); f2fma(acc[0][1], w0, x1);
            f2fma(acc[0][2], w0, x2); f2fma(acc[0][3], w0, x3);
            f2fma(acc[0][4], w0, x4); f2fma(acc[0][5], w0, x5);
            f2fma(acc[0][6], w0, x6); f2fma(acc[0][7], w0, x7);
            f2fma(acc[1][0], w1, x0); f2fma(acc[1][1], w1, x1);
            f2fma(acc[1][2], w1, x2); f2fma(acc[1][3], w1, x3);
            f2fma(acc[1][4], w1, x4); f2fma(acc[1][5], w1, x5);
            f2fma(acc[1][6], w1, x6); f2fma(acc[1][7], w1, x7);
        }
        if (gid) {
#pragma unroll
            for (int i = 0; i < 16; i++) pb[t * 17 + i] = acc[i >> 3][i & 7];
        }
        __syncthreads();
        if (!gid) {
#pragma unroll
            for (int op = 0; op < 2; op++) {
                u64t bd = *(const u64t*)(sm + SM_B2 + ot * 64 + o0 + 2 * op);
#pragma unroll
                for (int j = 0; j < 8; j++) {
                    f2add(acc[op][j], pb[t * 17 + op * 8 + j]);
                    f2add(acc[op][j], bd);
                }
                float lo[8], hi[8];
#pragma unroll
                for (int j = 0; j < 8; j++) {
                    float2 v = up(acc[op][j]); lo[j] = v.x; hi[j] = v.y;
                }
                int o_lo = ot * 64 + o0 + 2 * op;
                long ga0 = xwin + (long)o_lo * HWSZ + ((n0 >> 3) << 7);
                long ga1 = ga0 + HWSZ;
                float4 xi0 = *(const float4*)&x[ga0];
                float4 xi1 = *(const float4*)&x[ga0 + 4];
                float4 xi2 = *(const float4*)&x[ga1];
                float4 xi3 = *(const float4*)&x[ga1 + 4];
                *(float4*)&out[ga0]     = make_float4(lo[0] + xi0.x, lo[1] + xi0.y, lo[2] + xi0.z, lo[3] + xi0.w);
                *(float4*)&out[ga0 + 4] = make_float4(lo[4] + xi1.x, lo[5] + xi1.y, lo[6] + xi1.z, lo[7] + xi1.w);
                *(float4*)&out[ga1]     = make_float4(hi[0] + xi2.x, hi[1] + xi2.y, hi[2] + xi2.z, hi[3] + xi2.w);
                *(float4*)&out[ga1 + 4] = make_float4(hi[4] + xi3.x, hi[5] + xi3.y, hi[6] + xi3.z, hi[7] + xi3.w);
            }
        }
        __syncthreads();
    }
}

// ---------------------------------------------------------------------------
extern "C" void kernel_launch(void* const* d_in, const int* in_sizes, int n_in,
                              void* d_out, int out_size)
{
    const float* x            = (const float*)d_in[0];
    const float* bn_in_gamma  = (const float*)d_in[1];
    const float* bn_in_beta   = (const float*)d_in[2];
    const float* bn_in_mean   = (const float*)d_in[3];
    const float* bn_in_var    = (const float*)d_in[4];
    const float* in_proj_w    = (const float*)d_in[5];
    const float* qk_base_w    = (const float*)d_in[6];
    const float* q_head_w     = (const float*)d_in[7];
    const float* q_head_b     = (const float*)d_in[8];
    const float* k_head_w     = (const float*)d_in[9];
    const float* k_head_b     = (const float*)d_in[10];
    const float* v_w          = (const float*)d_in[11];
    const float* v_b          = (const float*)d_in[12];
    const float* o_w          = (const float*)d_in[13];
    const float* o_b          = (const float*)d_in[14];
    const float* out_proj_w   = (const float*)d_in[15];
    const float* bn_out_gamma = (const float*)d_in[16];
    const float* bn_out_beta  = (const float*)d_in[17];
    const float* bn_out_mean  = (const float*)d_in[18];
    const float* bn_out_var   = (const float*)d_in[19];
    const float* alpha        = (const float*)d_in[20];

    float* out = (float*)d_out;

    k_prep<<<1, 256>>>(bn_in_gamma, bn_in_beta, bn_in_mean, bn_in_var,
                       in_proj_w, out_proj_w,
                       bn_out_gamma, bn_out_beta, bn_out_mean, bn_out_var,
                       alpha, q_head_w, q_head_b, k_head_w, k_head_b);

    cudaFuncSetAttribute(k_fused, cudaFuncAttributeMaxDynamicSharedMemorySize,
                         SM_TOTAL * 4);
    k_fused<<<NWIN, 256, SM_TOTAL * 4>>>(x, out,
                                         qk_base_w, v_w, v_b, o_w, o_b);
}

// round 10
// speedup vs baseline: 1.3384x; 1.3384x over previous
#include <cuda_runtime.h>
#include <math.h>

#define BATCH 16
#define CCH   256
#define HWSZ  16384
#define RED   64
#define MID   32
#define NWIN  4096
#define ATT_SCALE 0.35355339059327373f   // 8^-0.5

typedef unsigned long long u64t;

// Folded weights (prepared by k_prep)
__device__ float g_W1t[CCH * RED];    // [c][o]  in_proj with BN folded
__device__ float g_b1[RED];
__device__ float g_Wqke[64 * 64];     // [c][o]  (q_head|k_head) @ qk_base, transposed
__device__ float g_bqk[64];
__device__ float g_W2e[MID * CCH];    // [m][o]  out_proj @ o_w, transposed, BN+sig folded
__device__ float g_b2e[CCH];

__device__ __forceinline__ u64t pk(float a) {
    u64t r; asm("mov.b64 %0, {%1,%1};" : "=l"(r) : "f"(a)); return r;
}
__device__ __forceinline__ void f2fma(u64t& d, u64t a, u64t b) {
    asm("fma.rn.f32x2 %0, %1, %2, %0;" : "+l"(d) : "l"(a), "l"(b));
}
__device__ __forceinline__ float2 up(u64t a) {
    float2 f; asm("mov.b64 {%0, %1}, %2;" : "=f"(f.x), "=f"(f.y) : "l"(a)); return f;
}

// ---------------------------------------------------------------------------
// k_prep: fold BNs/sigmoid AND adjacent linear layers
// ---------------------------------------------------------------------------
__global__ void k_prep(const float* __restrict__ gin,  const float* __restrict__ bin,
                       const float* __restrict__ min_, const float* __restrict__ vin,
                       const float* __restrict__ w_in, const float* __restrict__ w_out,
                       const float* __restrict__ gout, const float* __restrict__ bout,
                       const float* __restrict__ mout, const float* __restrict__ vout,
                       const float* __restrict__ alpha,
                       const float* __restrict__ qh,   const float* __restrict__ qb,
                       const float* __restrict__ kh,   const float* __restrict__ kb,
                       const float* __restrict__ qkb,  const float* __restrict__ ow,
                       const float* __restrict__ ob)
{
    int tid = threadIdx.x;
    float s = 1.f / (1.f + expf(-alpha[0]));

    // W1t[c][o] = in_proj_w[o][c] * inv_in[c]
    for (int idx = tid; idx < CCH * RED; idx += 256) {
        int c = idx >> 6, o = idx & 63;
        float inv = gin[c] * rsqrtf(vin[c] + 1e-5f);
        g_W1t[idx] = w_in[o * CCH + c] * inv;
    }
    if (tid < RED) {
        float a = 0.f;
        for (int c = 0; c < CCH; c++) {
            float inv = gin[c] * rsqrtf(vin[c] + 1e-5f);
            a += w_in[tid * CCH + c] * (bin[c] - min_[c] * inv);
        }
        g_b1[tid] = a;
    }
    // Wqke[c][o] = sum_u head[o][g(c)*8+u] * qkb[g(c)][u][c%16]
    for (int idx = tid; idx < 64 * 64; idx += 256) {
        int c = idx >> 6, o = idx & 63;
        int g = c >> 4, cc = c & 15;
        const float* head = (o < 32) ? (qh + o * 32) : (kh + (o - 32) * 32);
        float a = 0.f;
        for (int u = 0; u < 8; u++)
            a += head[g * 8 + u] * qkb[g * 128 + u * 16 + cc];
        g_Wqke[idx] = a;
    }
    if (tid < 64) g_bqk[tid] = (tid < 32) ? qb[tid] : kb[tid - 32];
    // W2e[m][o] = s*inv[o] * sum_t w_out[o][g(m)*16+t] * ow[g(m)][t][m%8]
    for (int idx = tid; idx < MID * CCH; idx += 256) {
        int m = idx >> 8, o = idx & 255;
        int g = m >> 3, mm = m & 7;
        float inv = gout[o] * rsqrtf(vout[o] + 1e-5f);
        float a = 0.f;
        for (int t = 0; t < 16; t++)
            a += w_out[o * RED + g * 16 + t] * ow[g * 128 + t * 8 + mm];
        g_W2e[m * CCH + o] = s * inv * a;
    }
    // b2e[o] = s*(bout - mout*inv) + s*inv * sum_r w_out[o][r]*ob[r]
    if (tid < 256) {
        float inv = gout[tid] * rsqrtf(vout[tid] + 1e-5f);
        float acc = 0.f;
        for (int r = 0; r < RED; r++) acc += w_out[tid * RED + r] * ob[r];
        g_b2e[tid] = s * (bout[tid] - mout[tid] * inv) + s * inv * acc;
    }
}

// ---------------------------------------------------------------------------
// SMEM layout (floats), phase-overlaid:
//   A: xchunk(4096) -> Wqke stage(4096) -> S(64x68=4352)
//   B: W1 stage(4096) -> [qs|ks](4096) -> W2e stage(2048)
//   C: xr(4096)
//   D: outs(2048)
//   U: vs(2048)
// ---------------------------------------------------------------------------
#define SM_A    0
#define SM_B    4352
#define SM_C    8448
#define SM_D    12544
#define SM_U    14592
#define SM_WV   16640   // 512
#define SM_BQK  17152   // 64
#define SM_BV   17216   // 32
#define SM_B1   17248   // 64
#define SM_B2   17312   // 256
#define SM_TOTAL 17568  // 70272 bytes -> 3 CTAs/SM

__global__ __launch_bounds__(256, 3) void k_fused(
    const float* __restrict__ x, float* __restrict__ out,
    const float* __restrict__ wv_g, const float* __restrict__ vb_g)
{
    extern __shared__ float sm[];
    const int tid = threadIdx.x;
    const int bw = blockIdx.x;
    const int b  = bw >> 8;
    const int hb = (bw >> 4) & 15;
    const int wb = bw & 15;
    const long winbase = (long)(hb * 8) * 128 + wb * 8;
    const long xwin = (long)b * CCH * HWSZ + winbase;

    // ---- small weights/biases to smem ----
    for (int i = tid; i < 512; i += 256) sm[SM_WV + i] = wv_g[i];
    if (tid < 64)       sm[SM_BQK + tid] = g_bqk[tid];
    else if (tid < 96)  sm[SM_BV + tid - 64] = vb_g[tid - 64];
    else if (tid < 160) sm[SM_B1 + tid - 96] = g_b1[tid - 96];
    sm[SM_B2 + tid] = g_b2e[tid];

    // uniform thread mapping: thread 4o x 4n
    const int oa = (tid >> 4) * 4;
    const int na = (tid & 15) * 4;

    // ================= in_proj: xr = W1t^T @ x_window (K=256) =================
    {
        u64t acc[2][4] = {{0,0,0,0},{0,0,0,0}};
        for (int kc = 0; kc < 4; kc++) {
            for (int idx = tid; idx < 1024; idx += 256)
                ((float4*)(sm + SM_B))[idx] = ((const float4*)(g_W1t + kc * 4096))[idx];
            for (int idx = tid; idx < 1024; idx += 256) {
                int c = idx >> 4, q = idx & 15;
                ((float4*)(sm + SM_A))[idx] =
                    *(const float4*)&x[xwin + (long)(kc * 64 + c) * HWSZ + ((q >> 1) << 7) + ((q & 1) << 2)];
            }
            __syncthreads();
#pragma unroll 8
            for (int k = 0; k < 64; k++) {
                const u64t* wp = (const u64t*)(sm + SM_B + k * 64 + oa);
                u64t w0 = wp[0], w1 = wp[1];
                float4 xv = *(const float4*)(sm + SM_A + k * 64 + na);
                u64t x0 = pk(xv.x), x1 = pk(xv.y), x2 = pk(xv.z), x3 = pk(xv.w);
                f2fma(acc[0][0], w0, x0); f2fma(acc[0][1], w0, x1);
                f2fma(acc[0][2], w0, x2); f2fma(acc[0][3], w0, x3);
                f2fma(acc[1][0], w1, x0); f2fma(acc[1][1], w1, x1);
                f2fma(acc[1][2], w1, x2); f2fma(acc[1][3], w1, x3);
            }
            __syncthreads();
        }
#pragma unroll
        for (int op = 0; op < 2; op++) {
            float ba = sm[SM_B1 + oa + op * 2], bb = sm[SM_B1 + oa + op * 2 + 1];
#pragma unroll
            for (int j = 0; j < 4; j++) {
                float2 v = up(acc[op][j]);
                sm[SM_C + (oa + op * 2)     * 64 + na + j] = v.x + ba;
                sm[SM_C + (oa + op * 2 + 1) * 64 + na + j] = v.y + bb;
            }
        }
    }
    __syncthreads();

    // ====== v = grouped conv (wv) on xr -> U ; stage Wqke -> A ======
    {
#pragma unroll
        for (int t2 = 0; t2 < 2; t2++) {
            int et = tid + 256 * t2;
            int m = et >> 4, nb = (et & 15) * 4, g = m >> 3;
            const float* wr2 = sm + SM_WV + g * 128 + (m & 7) * 16;
            float bv = sm[SM_BV + m];
            float4 av = make_float4(bv, bv, bv, bv);
#pragma unroll
            for (int i = 0; i < 16; i++) {
                float w2 = wr2[i];
                float4 xv = *(const float4*)(sm + SM_C + (g * 16 + i) * 64 + nb);
                av.x += w2 * xv.x; av.y += w2 * xv.y; av.z += w2 * xv.z; av.w += w2 * xv.w;
            }
            *(float4*)(sm + SM_U + m * 64 + nb) = av;
        }
        const float4* src = (const float4*)g_Wqke;
        for (int idx = tid; idx < 1024; idx += 256)
            ((float4*)(sm + SM_A))[idx] = src[idx];
    }
    __syncthreads();

    // ========== q|k : dense 64x64, K=64 GEMM on xr ==========
    {
        u64t acc[2][4] = {{0,0,0,0},{0,0,0,0}};
#pragma unroll 8
        for (int k = 0; k < 64; k++) {
            const u64t* wp = (const u64t*)(sm + SM_A + k * 64 + oa);
            u64t w0 = wp[0], w1 = wp[1];
            float4 xv = *(const float4*)(sm + SM_C + k * 64 + na);
            u64t x0 = pk(xv.x), x1 = pk(xv.y), x2 = pk(xv.z), x3 = pk(xv.w);
            f2fma(acc[0][0], w0, x0); f2fma(acc[0][1], w0, x1);
            f2fma(acc[0][2], w0, x2); f2fma(acc[0][3], w0, x3);
            f2fma(acc[1][0], w1, x0); f2fma(acc[1][1], w1, x1);
            f2fma(acc[1][2], w1, x2); f2fma(acc[1][3], w1, x3);
        }
#pragma unroll
        for (int op = 0; op < 2; op++) {
            float ba = sm[SM_BQK + oa + op * 2], bb = sm[SM_BQK + oa + op * 2 + 1];
#pragma unroll
            for (int j = 0; j < 4; j++) {
                float2 v = up(acc[op][j]);
                sm[SM_B + (oa + op * 2)     * 64 + na + j] = v.x + ba;
                sm[SM_B + (oa + op * 2 + 1) * 64 + na + j] = v.y + bb;
            }
        }
    }
    __syncthreads();

    // ================= attention, per head =================
    for (int h = 0; h < 4; h++) {
        // scores 4x4 register tile -> S (stride 68)
        {
            float sc[4][4];
#pragma unroll
            for (int a = 0; a < 4; a++)
#pragma unroll
                for (int c = 0; c < 4; c++) sc[a][c] = 0.f;
#pragma unroll
            for (int d = 0; d < 8; d++) {
                float4 q4 = *(const float4*)(sm + SM_B + (h * 8 + d) * 64 + oa);
                float4 k4 = *(const float4*)(sm + SM_B + 2048 + (h * 8 + d) * 64 + na);
                sc[0][0] += q4.x * k4.x; sc[0][1] += q4.x * k4.y; sc[0][2] += q4.x * k4.z; sc[0][3] += q4.x * k4.w;
                sc[1][0] += q4.y * k4.x; sc[1][1] += q4.y * k4.y; sc[1][2] += q4.y * k4.z; sc[1][3] += q4.y * k4.w;
                sc[2][0] += q4.z * k4.x; sc[2][1] += q4.z * k4.y; sc[2][2] += q4.z * k4.z; sc[2][3] += q4.z * k4.w;
                sc[3][0] += q4.w * k4.x; sc[3][1] += q4.w * k4.y; sc[3][2] += q4.w * k4.z; sc[3][3] += q4.w * k4.w;
            }
#pragma unroll
            for (int a = 0; a < 4; a++) {
                float4 ov = make_float4(sc[a][0] * ATT_SCALE, sc[a][1] * ATT_SCALE,
                                        sc[a][2] * ATT_SCALE, sc[a][3] * ATT_SCALE);
                *(float4*)(sm + SM_A + (oa + a) * 68 + na) = ov;
            }
        }
        __syncthreads();
        // softmax: 4 threads per row, shfl reduce
        {
            int row = tid >> 2, qd = tid & 3;
            float* Sr = sm + SM_A + row * 68 + qd * 16;
            float4 v0 = *(float4*)(Sr + 0), v1 = *(float4*)(Sr + 4);
            float4 v2 = *(float4*)(Sr + 8), v3 = *(float4*)(Sr + 12);
            float mx = fmaxf(fmaxf(fmaxf(v0.x, v0.y), fmaxf(v0.z, v0.w)),
                             fmaxf(fmaxf(v1.x, v1.y), fmaxf(v1.z, v1.w)));
            mx = fmaxf(mx, fmaxf(fmaxf(fmaxf(v2.x, v2.y), fmaxf(v2.z, v2.w)),
                                 fmaxf(fmaxf(v3.x, v3.y), fmaxf(v3.z, v3.w))));
            mx = fmaxf(mx, __shfl_xor_sync(0xffffffffu, mx, 1));
            mx = fmaxf(mx, __shfl_xor_sync(0xffffffffu, mx, 2));
            v0.x = __expf(v0.x - mx); v0.y = __expf(v0.y - mx); v0.z = __expf(v0.z - mx); v0.w = __expf(v0.w - mx);
            v1.x = __expf(v1.x - mx); v1.y = __expf(v1.y - mx); v1.z = __expf(v1.z - mx); v1.w = __expf(v1.w - mx);
            v2.x = __expf(v2.x - mx); v2.y = __expf(v2.y - mx); v2.z = __expf(v2.z - mx); v2.w = __expf(v2.w - mx);
            v3.x = __expf(v3.x - mx); v3.y = __expf(v3.y - mx); v3.z = __expf(v3.z - mx); v3.w = __expf(v3.w - mx);
            float s = (v0.x + v0.y + v0.z + v0.w) + (v1.x + v1.y + v1.z + v1.w)
                    + (v2.x + v2.y + v2.z + v2.w) + (v3.x + v3.y + v3.z + v3.w);
            s += __shfl_xor_sync(0xffffffffu, s, 1);
            s += __shfl_xor_sync(0xffffffffu, s, 2);
            float r = 1.f / s;
            v0.x *= r; v0.y *= r; v0.z *= r; v0.w *= r;
            v1.x *= r; v1.y *= r; v1.z *= r; v1.w *= r;
            v2.x *= r; v2.y *= r; v2.z *= r; v2.w *= r;
            v3.x *= r; v3.y *= r; v3.z *= r; v3.w *= r;
            *(float4*)(Sr + 0) = v0;  *(float4*)(Sr + 4) = v1;
            *(float4*)(Sr + 8) = v2;  *(float4*)(Sr + 12) = v3;
        }
        __syncthreads();
        // out = attn @ v : thread -> token i, rows r0, r0+1
        {
            int i = tid & 63, dq = tid >> 6;
            int r0 = h * 8 + dq * 2;
            const float* Sr = sm + SM_A + i * 68;
            float a0 = 0.f, a1 = 0.f;
#pragma unroll
            for (int j = 0; j < 64; j += 4) {
                float4 s4 = *(const float4*)(Sr + j);
                float4 w0 = *(const float4*)(sm + SM_U + r0 * 64 + j);
                float4 w1 = *(const float4*)(sm + SM_U + (r0 + 1) * 64 + j);
                a0 += s4.x * w0.x + s4.y * w0.y + s4.z * w0.z + s4.w * w0.w;
                a1 += s4.x * w1.x + s4.y * w1.y + s4.z * w1.z + s4.w * w1.w;
            }
            sm[SM_D + r0 * 64 + i]       = a0;
            sm[SM_D + (r0 + 1) * 64 + i] = a1;
        }
        __syncthreads();
    }

    // ====== out_proj folded with o-conv: 256 outs in 4 tiles, K=32 on outs ======
    const int ty0 = ((na >> 3) << 7);
    const int tx0 = (na & 7);
    for (int ot = 0; ot < 4; ot++) {
        // stage W2e slice [32][64] into B
        for (int idx = tid; idx < 512; idx += 256) {
            int m = idx >> 3, oq = idx & 7;
            ((float4*)(sm + SM_B))[idx] =
                *(const float4*)&g_W2e[m * 256 + ot * 64 + oq * 4];
        }
        __syncthreads();
        u64t acc[2][4] = {{0,0,0,0},{0,0,0,0}};
#pragma unroll 8
        for (int k = 0; k < 32; k++) {
            const u64t* wp = (const u64t*)(sm + SM_B + k * 64 + oa);
            u64t w0 = wp[0], w1 = wp[1];
            float4 xv = *(const float4*)(sm + SM_D + k * 64 + na);
            u64t x0 = pk(xv.x), x1 = pk(xv.y), x2 = pk(xv.z), x3 = pk(xv.w);
            f2fma(acc[0][0], w0, x0); f2fma(acc[0][1], w0, x1);
            f2fma(acc[0][2], w0, x2); f2fma(acc[0][3], w0, x3);
            f2fma(acc[1][0], w1, x0); f2fma(acc[1][1], w1, x1);
            f2fma(acc[1][2], w1, x2); f2fma(acc[1][3], w1, x3);
        }
        float r4[4][4];
#pragma unroll
        for (int op = 0; op < 2; op++)
#pragma unroll
            for (int j = 0; j < 4; j++) {
                float2 v = up(acc[op][j]);
                r4[op * 2][j] = v.x; r4[op * 2 + 1][j] = v.y;
            }
#pragma unroll
        for (int i2 = 0; i2 < 4; i2++) {
            int o = ot * 64 + oa + i2;
            long ga = xwin + (long)o * HWSZ + ty0 + tx0;
            float4 xi = *(const float4*)&x[ga];
            float bb = sm[SM_B2 + o];
            float4 ov = make_float4(r4[i2][0] + bb + xi.x, r4[i2][1] + bb + xi.y,
                                    r4[i2][2] + bb + xi.z, r4[i2][3] + bb + xi.w);
            *(float4*)&out[ga] = ov;
        }
        __syncthreads();
    }
}

// ---------------------------------------------------------------------------
extern "C" void kernel_launch(void* const* d_in, const int* in_sizes, int n_in,
                              void* d_out, int out_size)
{
    const float* x            = (const float*)d_in[0];
    const float* bn_in_gamma  = (const float*)d_in[1];
    const float* bn_in_beta   = (const float*)d_in[2];
    const float* bn_in_mean   = (const float*)d_in[3];
    const float* bn_in_var    = (const float*)d_in[4];
    const float* in_proj_w    = (const float*)d_in[5];
    const float* qk_base_w    = (const float*)d_in[6];
    const float* q_head_w     = (const float*)d_in[7];
    const float* q_head_b     = (const float*)d_in[8];
    const float* k_head_w     = (const float*)d_in[9];
    const float* k_head_b     = (const float*)d_in[10];
    const float* v_w          = (const float*)d_in[11];
    const float* v_b          = (const float*)d_in[12];
    const float* o_w          = (const float*)d_in[13];
    const float* o_b          = (const float*)d_in[14];
    const float* out_proj_w   = (const float*)d_in[15];
    const float* bn_out_gamma = (const float*)d_in[16];
    const float* bn_out_beta  = (const float*)d_in[17];
    const float* bn_out_mean  = (const float*)d_in[18];
    const float* bn_out_var   = (const float*)d_in[19];
    const float* alpha        = (const float*)d_in[20];

    float* out = (float*)d_out;

    k_prep<<<1, 256>>>(bn_in_gamma, bn_in_beta, bn_in_mean, bn_in_var,
                       in_proj_w, out_proj_w,
                       bn_out_gamma, bn_out_beta, bn_out_mean, bn_out_var,
                       alpha, q_head_w, q_head_b, k_head_w, k_head_b,
                       qk_base_w, o_w, o_b);

    cudaFuncSetAttribute(k_fused, cudaFuncAttributeMaxDynamicSharedMemorySize,
                         SM_TOTAL * 4);
    k_fused<<<NWIN, 256, SM_TOTAL * 4>>>(x, out, v_w, v_b);
}